// round 11
// baseline (speedup 1.0000x reference)
#include <cuda_runtime.h>
#include <math.h>
#include <stdint.h>

#define NN 50000
#define CC 128
#define HH 256
#define EE 600000

// ---- persistent scratch ----
__device__ float  g_xbuf[NN*CC];   // running residual x
__device__ float  g_obuf[NN*CC];   // agg + root (MLP input)
__device__ float  g_h1  [NN*HH];   // hidden after W1 (raw; LN fused into gemm2 loader)
__device__ float  g_gnstat[2*CC];
__device__ double g_lnstat[2];
__device__ int    g_deg [NN];
__device__ int    g_off [NN+1];
__device__ int    g_esrc[EE];

// ---- packed f32x2 helpers ----
__device__ __forceinline__ unsigned long long pack2(float x, float y){
    unsigned long long r;
    asm("mov.b64 %0, {%1, %2};" : "=l"(r) : "f"(x), "f"(y));
    return r;
}
__device__ __forceinline__ void unpack2(unsigned long long v, float& x, float& y){
    asm("mov.b64 {%0, %1}, %2;" : "=f"(x), "=f"(y) : "l"(v));
}
__device__ __forceinline__ unsigned long long pfma(unsigned long long a, unsigned long long b,
                                                   unsigned long long c){
    unsigned long long r;
    asm("fma.rn.f32x2 %0, %1, %2, %3;" : "=l"(r) : "l"(a), "l"(b), "l"(c));
    return r;
}

// =================== CSR build (dst-grouped), once per launch ===================
__global__ void k_zero_deg(int N){
    int gid = blockIdx.x*blockDim.x + threadIdx.x;
    for (int i = gid; i < N; i += gridDim.x*blockDim.x) g_deg[i] = 0;
    if (gid < 2*CC) g_gnstat[gid] = 0.f;            // zero for k_copy's fused stats
}
__global__ void k_hist(const int* __restrict__ dst, int E){
    for (int e = blockIdx.x*blockDim.x + threadIdx.x; e < E; e += gridDim.x*blockDim.x)
        atomicAdd(&g_deg[dst[e]], 1);
}
__global__ void k_scan(int N){
    __shared__ int part[1024];
    int t = threadIdx.x;
    int chunk = (N + 1023)/1024;
    int beg = t*chunk, end = min(beg + chunk, N);
    int s = 0;
    for (int i = beg; i < end; i++) s += g_deg[i];
    part[t] = s; __syncthreads();
    for (int o = 1; o < 1024; o <<= 1){
        int v = (t >= o) ? part[t-o] : 0;
        __syncthreads();
        part[t] += v;
        __syncthreads();
    }
    int base = (t == 0) ? 0 : part[t-1];
    for (int i = beg; i < end; i++){ g_off[i] = base; base += g_deg[i]; g_deg[i] = 0; }
    if (t == 1023) g_off[N] = part[1023];
}
__global__ void k_scatter(const int* __restrict__ src, const int* __restrict__ dst, int E){
    for (int e = blockIdx.x*blockDim.x + threadIdx.x; e < E; e += gridDim.x*blockDim.x){
        int d = dst[e];
        int pos = atomicAdd(&g_deg[d], 1);
        g_esrc[g_off[d] + pos] = src[e];
    }
}

// =================== copy + fused layer-0 GraphNorm stats ===================
__global__ void k_copy_stats(const float* __restrict__ x, int N){
    int c = threadIdx.x;
    float s1 = 0.f, s2 = 0.f;
    for (int r = blockIdx.x; r < N; r += gridDim.x){
        float v = x[(size_t)r*CC + c];
        g_xbuf[(size_t)r*CC + c] = v;
        s1 += v; s2 += v*v;
    }
    atomicAdd(&g_gnstat[c],    s1);
    atomicAdd(&g_gnstat[CC+c], s2);
}

// =================== fused GraphNorm+ReLU+softmax-aggregate (CSR gather, no atomics) ===================
// h_j = max(scale_c * x_j + off_c, 0) computed inline from g_xbuf (gn_apply eliminated).
// Also zeroes LN stats for this layer (block 0).
__global__ void k_agg(const float* __restrict__ t,
                      const float* __restrict__ gw, const float* __restrict__ gb,
                      const float* __restrict__ ga, int l, int N){
    if (blockIdx.x == 0 && threadIdx.x < 2) g_lnstat[threadIdx.x] = 0.0;
    int d = blockIdx.x*8 + (threadIdx.x >> 5);
    if (d >= N) return;
    int lane = threadIdx.x & 31;

    // per-channel GN constants for this lane's 4 channels
    float invN = 1.f/(float)N;
    float4 sv1 = *((const float4*)&g_gnstat[lane*4]);
    float4 sv2 = *((const float4*)&g_gnstat[CC + lane*4]);
    float4 av  = *((const float4*)&ga[l*CC + lane*4]);
    float4 gwv = *((const float4*)&gw[l*CC + lane*4]);
    float4 gbv = *((const float4*)&gb[l*CC + lane*4]);
    float4 scale, off;
    {
        float m, var;
        m = sv1.x*invN; var = sv2.x*invN - 2.f*av.x*m*m + av.x*av.x*m*m;
        scale.x = gwv.x*rsqrtf(var + 1e-5f); off.x = gbv.x - scale.x*(av.x*m);
        m = sv1.y*invN; var = sv2.y*invN - 2.f*av.y*m*m + av.y*av.y*m*m;
        scale.y = gwv.y*rsqrtf(var + 1e-5f); off.y = gbv.y - scale.y*(av.y*m);
        m = sv1.z*invN; var = sv2.z*invN - 2.f*av.z*m*m + av.z*av.z*m*m;
        scale.z = gwv.z*rsqrtf(var + 1e-5f); off.z = gbv.z - scale.z*(av.z*m);
        m = sv1.w*invN; var = sv2.w*invN - 2.f*av.w*m*m + av.w*av.w*m*m;
        scale.w = gwv.w*rsqrtf(var + 1e-5f); off.w = gbv.w - scale.w*(av.w*m);
    }

    int beg = g_off[d], end = g_off[d+1];
    float tv = t[l];
    float4 num = make_float4(0.f,0.f,0.f,0.f);
    float4 den = make_float4(0.f,0.f,0.f,0.f);
    for (int j = beg; j < end; j++){
        int s0 = g_esrc[j];
        float4 v0 = *((const float4*)&g_xbuf[(size_t)s0*CC] + lane);
        float hx = fmaxf(fmaf(scale.x, v0.x, off.x), 0.f);
        float hy = fmaxf(fmaf(scale.y, v0.y, off.y), 0.f);
        float hz = fmaxf(fmaf(scale.z, v0.z, off.z), 0.f);
        float hw = fmaxf(fmaf(scale.w, v0.w, off.w), 0.f);
        float mx = hx + 1e-7f, my = hy + 1e-7f, mz = hz + 1e-7f, mw = hw + 1e-7f;
        float ex = __expf(tv*mx), ey = __expf(tv*my), ez = __expf(tv*mz), ew = __expf(tv*mw);
        num.x = fmaf(mx, ex, num.x); den.x += ex;
        num.y = fmaf(my, ey, num.y); den.y += ey;
        num.z = fmaf(mz, ez, num.z); den.z += ez;
        num.w = fmaf(mw, ew, num.w); den.w += ew;
    }
    float4 vd = *((const float4*)&g_xbuf[(size_t)d*CC] + lane);
    float hdx = fmaxf(fmaf(scale.x, vd.x, off.x), 0.f);
    float hdy = fmaxf(fmaf(scale.y, vd.y, off.y), 0.f);
    float hdz = fmaxf(fmaf(scale.z, vd.z, off.z), 0.f);
    float hdw = fmaxf(fmaf(scale.w, vd.w, off.w), 0.f);
    float4 o;
    o.x = num.x/(den.x + 1e-16f) + hdx;
    o.y = num.y/(den.y + 1e-16f) + hdy;
    o.z = num.z/(den.z + 1e-16f) + hdz;
    o.w = num.w/(den.w + 1e-16f) + hdw;
    *((float4*)&g_obuf[(size_t)d*CC] + lane) = o;
}

// =================== 128x128x16 double-buffered GEMM, 8x8 microtile, f32x2 FMA ===================
// MODE 0: g_h1 = obuf@W1 + b1; fused global-LN stats; zeroes gnstat for gemm2
// MODE 1: g_xbuf += relu(LN(g_h1))@W2 + b2; fused per-channel GN stats of final x
template<int MODE>
__device__ __forceinline__ void gemm128(const float* __restrict__ A, const float* __restrict__ B,
                                        const float* __restrict__ bias, float* __restrict__ Cout,
                                        int M, int Nn, int K,
                                        const float* __restrict__ lnw, const float* __restrict__ lnb){
    __shared__ float As[2][16][132];
    __shared__ float Bs[2][16][132];
    int tid = threadIdx.x;                    // 256
    int bm = blockIdx.y*128, bn = blockIdx.x*128;
    int ty = tid >> 4, tx = tid & 15;
    int lane = tid & 31;

    if (MODE == 0 && tid < 2*CC && blockIdx.x == 0 && blockIdx.y == 0)
        g_gnstat[tid] = 0.f;                  // ready for gemm2's fused GN stats

    float mean = 0.f, inv = 0.f;
    if (MODE == 1){
        double cnt = (double)M * (double)K;
        double mu  = g_lnstat[0]/cnt;
        double var = g_lnstat[1]/cnt - mu*mu;
        mean = (float)mu;
        inv  = 1.f/((float)sqrt(fmax(var, 0.0)) + 1e-5f);
    }

    int a_r  = tid >> 2;          // 0..63 (+64)
    int a_k  = (tid & 3)*4;
    int b_k  = tid >> 5;          // 0..7 (+8)
    int b_c  = (tid & 31)*4;

    float4 ra[2], rb[2];
    auto ldA = [&](int k0){
        #pragma unroll
        for (int i = 0; i < 2; i++){
            int row = bm + a_r + i*64;
            float4 av = make_float4(0.f,0.f,0.f,0.f);
            if (row < M){
                av = *(const float4*)&A[(size_t)row*K + k0 + a_k];
                if (MODE == 1){
                    int c = k0 + a_k;
                    av.x = fmaxf(fmaf((av.x-mean)*inv, __ldg(&lnw[c+0]), __ldg(&lnb[c+0])), 0.f);
                    av.y = fmaxf(fmaf((av.y-mean)*inv, __ldg(&lnw[c+1]), __ldg(&lnb[c+1])), 0.f);
                    av.z = fmaxf(fmaf((av.z-mean)*inv, __ldg(&lnw[c+2]), __ldg(&lnb[c+2])), 0.f);
                    av.w = fmaxf(fmaf((av.w-mean)*inv, __ldg(&lnw[c+3]), __ldg(&lnb[c+3])), 0.f);
                }
            }
            ra[i] = av;
        }
    };
    auto ldB = [&](int k0){
        #pragma unroll
        for (int i = 0; i < 2; i++)
            rb[i] = *(const float4*)&B[(size_t)(k0 + b_k + i*8)*Nn + bn + b_c];
    };
    auto stAB = [&](int buf){
        #pragma unroll
        for (int i = 0; i < 2; i++){
            As[buf][a_k+0][a_r + i*64] = ra[i].x;
            As[buf][a_k+1][a_r + i*64] = ra[i].y;
            As[buf][a_k+2][a_r + i*64] = ra[i].z;
            As[buf][a_k+3][a_r + i*64] = ra[i].w;
            *(float4*)&Bs[buf][b_k + i*8][b_c] = rb[i];
        }
    };

    unsigned long long acc[8][4];
    #pragma unroll
    for (int i = 0; i < 8; i++)
        #pragma unroll
        for (int j = 0; j < 4; j++) acc[i][j] = 0ull;

    ldA(0); ldB(0); stAB(0);
    __syncthreads();

    int KT = K >> 4;
    for (int kt = 0; kt < KT; kt++){
        int cbuf = kt & 1;
        if (kt + 1 < KT){ ldA((kt+1)<<4); ldB((kt+1)<<4); }
        #pragma unroll
        for (int k = 0; k < 16; k++){
            float4 a0 = *(const float4*)&As[cbuf][k][ty*8];
            float4 a1 = *(const float4*)&As[cbuf][k][ty*8+4];
            // B pairs read directly as 64-bit lanes (no packing movs)
            ulonglong2 bb0 = *(const ulonglong2*)&Bs[cbuf][k][tx*8];
            ulonglong2 bb1 = *(const ulonglong2*)&Bs[cbuf][k][tx*8+4];
            unsigned long long bp[4] = { bb0.x, bb0.y, bb1.x, bb1.y };
            float a[8] = {a0.x,a0.y,a0.z,a0.w,a1.x,a1.y,a1.z,a1.w};
            #pragma unroll
            for (int i = 0; i < 8; i++){
                unsigned long long ad = pack2(a[i], a[i]);
                #pragma unroll
                for (int j = 0; j < 4; j++) acc[i][j] = pfma(ad, bp[j], acc[i][j]);
            }
        }
        if (kt + 1 < KT){ stAB((kt+1) & 1); }
        __syncthreads();
    }

    float bv[8];
    #pragma unroll
    for (int j = 0; j < 8; j++) bv[j] = bias[bn + tx*8 + j];

    float s1 = 0.f, s2 = 0.f;          // MODE 0: LN scalar stats
    float cs1[8], cs2[8];              // MODE 1: per-column GN stats
    #pragma unroll
    for (int j = 0; j < 8; j++){ cs1[j] = 0.f; cs2[j] = 0.f; }

    #pragma unroll
    for (int i = 0; i < 8; i++){
        int row = bm + ty*8 + i;
        if (row >= M) continue;
        size_t base = (size_t)row*Nn + bn + tx*8;
        #pragma unroll
        for (int h = 0; h < 2; h++){
            float4 r;
            unpack2(acc[i][h*2+0], r.x, r.y);
            unpack2(acc[i][h*2+1], r.z, r.w);
            r.x += bv[h*4+0]; r.y += bv[h*4+1];
            r.z += bv[h*4+2]; r.w += bv[h*4+3];
            if (MODE == 0){
                s1 += r.x + r.y + r.z + r.w;
                s2 += r.x*r.x + r.y*r.y + r.z*r.z + r.w*r.w;
            } else {
                float4 old = *(float4*)&Cout[base + h*4];
                r.x += old.x; r.y += old.y; r.z += old.z; r.w += old.w;
                cs1[h*4+0] += r.x; cs2[h*4+0] += r.x*r.x;
                cs1[h*4+1] += r.y; cs2[h*4+1] += r.y*r.y;
                cs1[h*4+2] += r.z; cs2[h*4+2] += r.z*r.z;
                cs1[h*4+3] += r.w; cs2[h*4+3] += r.w*r.w;
            }
            *(float4*)&Cout[base + h*4] = r;
        }
    }
    if (MODE == 0){
        #pragma unroll
        for (int o = 16; o > 0; o >>= 1){
            s1 += __shfl_xor_sync(0xFFFFFFFFu, s1, o);
            s2 += __shfl_xor_sync(0xFFFFFFFFu, s2, o);
        }
        if (lane == 0){
            atomicAdd(&g_lnstat[0], (double)s1);
            atomicAdd(&g_lnstat[1], (double)s2);
        }
    } else {
        // combine the two ty-rows sharing a warp (lanes l and l^16 have the same tx)
        #pragma unroll
        for (int j = 0; j < 8; j++){
            cs1[j] += __shfl_xor_sync(0xFFFFFFFFu, cs1[j], 16);
            cs2[j] += __shfl_xor_sync(0xFFFFFFFFu, cs2[j], 16);
        }
        if (lane < 16){
            int col = bn + tx*8;
            #pragma unroll
            for (int j = 0; j < 8; j++){
                atomicAdd(&g_gnstat[col + j],      cs1[j]);
                atomicAdd(&g_gnstat[CC + col + j], cs2[j]);
            }
        }
    }
}

__global__ void __launch_bounds__(256) k_gemm1(const float* __restrict__ B, const float* __restrict__ bias, int M){
    gemm128<0>(g_obuf, B, bias, g_h1, M, HH, CC, nullptr, nullptr);
}
__global__ void __launch_bounds__(256) k_gemm2(const float* __restrict__ B, const float* __restrict__ bias,
                                               const float* __restrict__ lnw, const float* __restrict__ lnb, int M){
    gemm128<1>(g_h1, B, bias, g_xbuf, M, CC, HH, lnw, lnb);
}

// out[n] = x[n,:] . lin_w + lin_b  (warp per node)
__global__ void k_final(const float* __restrict__ lw, const float* __restrict__ lb,
                        float* __restrict__ out, int N){
    int r = blockIdx.x*8 + (threadIdx.x >> 5);
    if (r >= N) return;
    int lane = threadIdx.x & 31;
    float4 v = ((const float4*)&g_xbuf[(size_t)r*CC])[lane];
    float4 w = ((const float4*)lw)[lane];
    float s = v.x*w.x + v.y*w.y + v.z*w.z + v.w*w.w;
    #pragma unroll
    for (int o = 16; o > 0; o >>= 1) s += __shfl_xor_sync(0xFFFFFFFFu, s, o);
    if (lane == 0) out[r] = s + lb[0];
}

extern "C" void kernel_launch(void* const* d_in, const int* in_sizes, int n_in,
                              void* d_out, int out_size){
    const float* x    = (const float*)d_in[0];
    const int*   src  = (const int*)  d_in[1];
    const int*   dst  = (const int*)  d_in[2];
    const float* W1   = (const float*)d_in[3];
    const float* b1   = (const float*)d_in[4];
    const float* lnw  = (const float*)d_in[5];
    const float* lnb  = (const float*)d_in[6];
    const float* W2   = (const float*)d_in[7];
    const float* b2   = (const float*)d_in[8];
    const float* t    = (const float*)d_in[9];
    const float* gnw  = (const float*)d_in[10];
    const float* gnb  = (const float*)d_in[11];
    const float* gna  = (const float*)d_in[12];
    const float* linw = (const float*)d_in[13];
    const float* linb = (const float*)d_in[14];
    float* out = (float*)d_out;

    int N = in_sizes[0]/CC;
    int E = in_sizes[1];
    int e_blocks  = (E + 255)/256;

    // CSR build (per launch; deterministic); scan resets cursors; zero_deg also zeroes gnstat
    k_zero_deg<<<(N+255)/256, 256>>>(N);
    k_hist<<<e_blocks, 256>>>(dst, E);
    k_scan<<<1, 1024>>>(N);
    k_scatter<<<e_blocks, 256>>>(src, dst, E);

    k_copy_stats<<<512, CC>>>(x, N);   // copy + layer-0 GN stats

    for (int l = 0; l < 4; l++){
        // k_agg: GN+ReLU fused into gather; zeroes lnstat
        k_agg<<<(N+7)/8, 256>>>(t, gnw, gnb, gna, l, N);
        k_gemm1<<<dim3(HH/128, (N+127)/128), 256>>>(W1 + (size_t)l*CC*HH, b1 + (size_t)l*HH, N); // LN stats, zeroes gnstat
        k_gemm2<<<dim3(CC/128, (N+127)/128), 256>>>(W2 + (size_t)l*HH*CC, b2 + (size_t)l*CC,
                                                    lnw + (size_t)l*HH, lnb + (size_t)l*HH, N);  // GN stats
    }
    k_final<<<(N+7)/8, 256>>>(linw, linb, out, N);
}

// round 15
// speedup vs baseline: 1.5094x; 1.5094x over previous
#include <cuda_runtime.h>
#include <math.h>
#include <stdint.h>

#define NN 50000
#define CC 128
#define HH 256
#define EE 600000

// ---- persistent scratch ----
__device__ float  g_xbuf[NN*CC];   // running residual x
__device__ float  g_obuf[NN*CC];   // agg + root (MLP input)
__device__ float  g_h1  [NN*HH];   // hidden after W1 (raw; LN fused into gemm2 loader)
__device__ float  g_gnstat[2*CC];
__device__ double g_lnstat[2];
__device__ int    g_deg [NN];
__device__ int    g_off [NN+1];
__device__ int    g_esrc[EE];

// ---- packed f32x2 helpers ----
__device__ __forceinline__ unsigned long long pack2(float x, float y){
    unsigned long long r;
    asm("mov.b64 %0, {%1, %2};" : "=l"(r) : "f"(x), "f"(y));
    return r;
}
__device__ __forceinline__ void unpack2(unsigned long long v, float& x, float& y){
    asm("mov.b64 {%0, %1}, %2;" : "=f"(x), "=f"(y) : "l"(v));
}
__device__ __forceinline__ unsigned long long pfma(unsigned long long a, unsigned long long b,
                                                   unsigned long long c){
    unsigned long long r;
    asm("fma.rn.f32x2 %0, %1, %2, %3;" : "=l"(r) : "l"(a), "l"(b), "l"(c));
    return r;
}

// =================== CSR build (dst-grouped), once per launch ===================
__global__ void k_zero_deg(int N){
    for (int i = blockIdx.x*blockDim.x + threadIdx.x; i < N; i += gridDim.x*blockDim.x)
        g_deg[i] = 0;
}
__global__ void k_hist(const int* __restrict__ dst, int E){
    for (int e = blockIdx.x*blockDim.x + threadIdx.x; e < E; e += gridDim.x*blockDim.x)
        atomicAdd(&g_deg[dst[e]], 1);
}
__global__ void k_scan(int N){
    __shared__ int part[1024];
    int t = threadIdx.x;
    int chunk = (N + 1023)/1024;
    int beg = t*chunk, end = min(beg + chunk, N);
    int s = 0;
    for (int i = beg; i < end; i++) s += g_deg[i];
    part[t] = s; __syncthreads();
    for (int o = 1; o < 1024; o <<= 1){
        int v = (t >= o) ? part[t-o] : 0;
        __syncthreads();
        part[t] += v;
        __syncthreads();
    }
    int base = (t == 0) ? 0 : part[t-1];
    for (int i = beg; i < end; i++){ g_off[i] = base; base += g_deg[i]; g_deg[i] = 0; }
    if (t == 1023) g_off[N] = part[1023];
}
__global__ void k_scatter(const int* __restrict__ src, const int* __restrict__ dst, int E){
    for (int e = blockIdx.x*blockDim.x + threadIdx.x; e < E; e += gridDim.x*blockDim.x){
        int d = dst[e];
        int pos = atomicAdd(&g_deg[d], 1);
        g_esrc[g_off[d] + pos] = src[e];
    }
}

// =================== elementwise / norm kernels (R5 scheme) ===================
__global__ void k_copy(const float* __restrict__ x, int n){
    for (int i = blockIdx.x*blockDim.x + threadIdx.x; i < n; i += gridDim.x*blockDim.x)
        g_xbuf[i] = x[i];
}
__global__ void k_zero_stats(){
    int t = threadIdx.x;
    if (t < 2*CC) g_gnstat[t] = 0.f;
    if (t == 0){ g_lnstat[0] = 0.0; g_lnstat[1] = 0.0; }
}
__global__ void k_gn_stats(int N){
    int c = threadIdx.x;          // 128 threads = channels
    float s1 = 0.f, s2 = 0.f;
    for (int r = blockIdx.x; r < N; r += gridDim.x){
        float v = g_xbuf[(size_t)r*CC + c];
        s1 += v; s2 += v*v;
    }
    atomicAdd(&g_gnstat[c],    s1);
    atomicAdd(&g_gnstat[CC+c], s2);
}

// =================== fused GraphNorm+ReLU+softmax-aggregate (CSR gather) ===================
// h_j = max(scale_c*x_j + off_c, 0) inline from g_xbuf (gn_apply eliminated). Unroll-2.
__global__ void k_agg(const float* __restrict__ t,
                      const float* __restrict__ gw, const float* __restrict__ gb,
                      const float* __restrict__ ga, int l, int N){
    int d = blockIdx.x*8 + (threadIdx.x >> 5);
    if (d >= N) return;
    int lane = threadIdx.x & 31;

    // per-lane GN constants (4 channels)
    float invN = 1.f/(float)N;
    float4 sv1 = *((const float4*)&g_gnstat[lane*4]);
    float4 sv2 = *((const float4*)&g_gnstat[CC + lane*4]);
    float4 av  = *((const float4*)&ga[l*CC + lane*4]);
    float4 gwv = *((const float4*)&gw[l*CC + lane*4]);
    float4 gbv = *((const float4*)&gb[l*CC + lane*4]);
    float4 scale, off;
    {
        float m, var;
        m = sv1.x*invN; var = sv2.x*invN - 2.f*av.x*m*m + av.x*av.x*m*m;
        scale.x = gwv.x*rsqrtf(var + 1e-5f); off.x = gbv.x - scale.x*(av.x*m);
        m = sv1.y*invN; var = sv2.y*invN - 2.f*av.y*m*m + av.y*av.y*m*m;
        scale.y = gwv.y*rsqrtf(var + 1e-5f); off.y = gbv.y - scale.y*(av.y*m);
        m = sv1.z*invN; var = sv2.z*invN - 2.f*av.z*m*m + av.z*av.z*m*m;
        scale.z = gwv.z*rsqrtf(var + 1e-5f); off.z = gbv.z - scale.z*(av.z*m);
        m = sv1.w*invN; var = sv2.w*invN - 2.f*av.w*m*m + av.w*av.w*m*m;
        scale.w = gwv.w*rsqrtf(var + 1e-5f); off.w = gbv.w - scale.w*(av.w*m);
    }

    int beg = g_off[d], end = g_off[d+1];
    float tv = t[l];
    float4 num = make_float4(0.f,0.f,0.f,0.f);
    float4 den = make_float4(0.f,0.f,0.f,0.f);
    int j = beg;
    for (; j + 1 < end; j += 2){
        int s0 = g_esrc[j], s1i = g_esrc[j+1];
        float4 v0 = *((const float4*)&g_xbuf[(size_t)s0*CC] + lane);
        float4 v1 = *((const float4*)&g_xbuf[(size_t)s1i*CC] + lane);
        float m0x = fmaxf(fmaf(scale.x, v0.x, off.x), 0.f) + 1e-7f;
        float m0y = fmaxf(fmaf(scale.y, v0.y, off.y), 0.f) + 1e-7f;
        float m0z = fmaxf(fmaf(scale.z, v0.z, off.z), 0.f) + 1e-7f;
        float m0w = fmaxf(fmaf(scale.w, v0.w, off.w), 0.f) + 1e-7f;
        float m1x = fmaxf(fmaf(scale.x, v1.x, off.x), 0.f) + 1e-7f;
        float m1y = fmaxf(fmaf(scale.y, v1.y, off.y), 0.f) + 1e-7f;
        float m1z = fmaxf(fmaf(scale.z, v1.z, off.z), 0.f) + 1e-7f;
        float m1w = fmaxf(fmaf(scale.w, v1.w, off.w), 0.f) + 1e-7f;
        float e0x=__expf(tv*m0x), e0y=__expf(tv*m0y), e0z=__expf(tv*m0z), e0w=__expf(tv*m0w);
        float e1x=__expf(tv*m1x), e1y=__expf(tv*m1y), e1z=__expf(tv*m1z), e1w=__expf(tv*m1w);
        num.x = fmaf(m0x,e0x,fmaf(m1x,e1x,num.x)); den.x += e0x+e1x;
        num.y = fmaf(m0y,e0y,fmaf(m1y,e1y,num.y)); den.y += e0y+e1y;
        num.z = fmaf(m0z,e0z,fmaf(m1z,e1z,num.z)); den.z += e0z+e1z;
        num.w = fmaf(m0w,e0w,fmaf(m1w,e1w,num.w)); den.w += e0w+e1w;
    }
    if (j < end){
        int s0 = g_esrc[j];
        float4 v0 = *((const float4*)&g_xbuf[(size_t)s0*CC] + lane);
        float mx = fmaxf(fmaf(scale.x, v0.x, off.x), 0.f) + 1e-7f;
        float my = fmaxf(fmaf(scale.y, v0.y, off.y), 0.f) + 1e-7f;
        float mz = fmaxf(fmaf(scale.z, v0.z, off.z), 0.f) + 1e-7f;
        float mw = fmaxf(fmaf(scale.w, v0.w, off.w), 0.f) + 1e-7f;
        float ex=__expf(tv*mx), ey=__expf(tv*my), ez=__expf(tv*mz), ew=__expf(tv*mw);
        num.x = fmaf(mx,ex,num.x); den.x += ex;
        num.y = fmaf(my,ey,num.y); den.y += ey;
        num.z = fmaf(mz,ez,num.z); den.z += ez;
        num.w = fmaf(mw,ew,num.w); den.w += ew;
    }
    float4 vd = *((const float4*)&g_xbuf[(size_t)d*CC] + lane);
    float hdx = fmaxf(fmaf(scale.x, vd.x, off.x), 0.f);
    float hdy = fmaxf(fmaf(scale.y, vd.y, off.y), 0.f);
    float hdz = fmaxf(fmaf(scale.z, vd.z, off.z), 0.f);
    float hdw = fmaxf(fmaf(scale.w, vd.w, off.w), 0.f);
    float4 o;
    o.x = num.x/(den.x+1e-16f) + hdx;
    o.y = num.y/(den.y+1e-16f) + hdy;
    o.z = num.z/(den.z+1e-16f) + hdz;
    o.w = num.w/(den.w+1e-16f) + hdw;
    *((float4*)&g_obuf[(size_t)d*CC] + lane) = o;
}

// =================== 128x128x16 double-buffered GEMM, 8x8 microtile, f32x2 FMA (R5 exact) ===================
// MODE 0: g_h1 = obuf@W1 + b1, fused global-LN statistics
// MODE 1: g_xbuf += relu(LN(g_h1))@W2 + b2 (LN+relu fused into A loader)
template<int MODE>
__device__ __forceinline__ void gemm128(const float* __restrict__ A, const float* __restrict__ B,
                                        const float* __restrict__ bias, float* __restrict__ Cout,
                                        int M, int Nn, int K,
                                        const float* __restrict__ lnw, const float* __restrict__ lnb){
    __shared__ float As[2][16][132];
    __shared__ float Bs[2][16][132];
    int tid = threadIdx.x;                    // 256
    int bm = blockIdx.y*128, bn = blockIdx.x*128;
    int ty = tid >> 4, tx = tid & 15;

    float mean = 0.f, inv = 0.f;
    if (MODE == 1){
        double cnt = (double)M * (double)K;
        double mu  = g_lnstat[0]/cnt;
        double var = g_lnstat[1]/cnt - mu*mu;
        mean = (float)mu;
        inv  = 1.f/((float)sqrt(fmax(var, 0.0)) + 1e-5f);
    }

    int a_r  = tid >> 2;          // 0..63 (+64)
    int a_k  = (tid & 3)*4;
    int b_k  = tid >> 5;          // 0..7 (+8)
    int b_c  = (tid & 31)*4;

    float4 ra[2], rb[2];
    auto ldA = [&](int k0){
        #pragma unroll
        for (int i = 0; i < 2; i++){
            int row = bm + a_r + i*64;
            float4 av = make_float4(0.f,0.f,0.f,0.f);
            if (row < M){
                av = *(const float4*)&A[(size_t)row*K + k0 + a_k];
                if (MODE == 1){
                    int c = k0 + a_k;
                    av.x = fmaxf(fmaf((av.x-mean)*inv, __ldg(&lnw[c+0]), __ldg(&lnb[c+0])), 0.f);
                    av.y = fmaxf(fmaf((av.y-mean)*inv, __ldg(&lnw[c+1]), __ldg(&lnb[c+1])), 0.f);
                    av.z = fmaxf(fmaf((av.z-mean)*inv, __ldg(&lnw[c+2]), __ldg(&lnb[c+2])), 0.f);
                    av.w = fmaxf(fmaf((av.w-mean)*inv, __ldg(&lnw[c+3]), __ldg(&lnb[c+3])), 0.f);
                }
            }
            ra[i] = av;
        }
    };
    auto ldB = [&](int k0){
        #pragma unroll
        for (int i = 0; i < 2; i++)
            rb[i] = *(const float4*)&B[(size_t)(k0 + b_k + i*8)*Nn + bn + b_c];
    };
    auto stAB = [&](int buf){
        #pragma unroll
        for (int i = 0; i < 2; i++){
            As[buf][a_k+0][a_r + i*64] = ra[i].x;
            As[buf][a_k+1][a_r + i*64] = ra[i].y;
            As[buf][a_k+2][a_r + i*64] = ra[i].z;
            As[buf][a_k+3][a_r + i*64] = ra[i].w;
            *(float4*)&Bs[buf][b_k + i*8][b_c] = rb[i];
        }
    };

    unsigned long long acc[8][4];
    #pragma unroll
    for (int i = 0; i < 8; i++)
        #pragma unroll
        for (int j = 0; j < 4; j++) acc[i][j] = 0ull;

    ldA(0); ldB(0); stAB(0);
    __syncthreads();

    int KT = K >> 4;
    for (int kt = 0; kt < KT; kt++){
        int cbuf = kt & 1;
        if (kt + 1 < KT){ ldA((kt+1)<<4); ldB((kt+1)<<4); }
        #pragma unroll
        for (int k = 0; k < 16; k++){
            float4 a0 = *(const float4*)&As[cbuf][k][ty*8];
            float4 a1 = *(const float4*)&As[cbuf][k][ty*8+4];
            float4 b0 = *(const float4*)&Bs[cbuf][k][tx*8];
            float4 b1 = *(const float4*)&Bs[cbuf][k][tx*8+4];
            unsigned long long bp[4] = { pack2(b0.x,b0.y), pack2(b0.z,b0.w),
                                         pack2(b1.x,b1.y), pack2(b1.z,b1.w) };
            float a[8] = {a0.x,a0.y,a0.z,a0.w,a1.x,a1.y,a1.z,a1.w};
            #pragma unroll
            for (int i = 0; i < 8; i++){
                unsigned long long ad = pack2(a[i], a[i]);
                #pragma unroll
                for (int j = 0; j < 4; j++) acc[i][j] = pfma(ad, bp[j], acc[i][j]);
            }
        }
        if (kt + 1 < KT){ stAB((kt+1) & 1); }
        __syncthreads();
    }

    float bv[8];
    #pragma unroll
    for (int j = 0; j < 8; j++) bv[j] = bias[bn + tx*8 + j];

    float s1 = 0.f, s2 = 0.f;   // LN stats (MODE 0)
    #pragma unroll
    for (int i = 0; i < 8; i++){
        int row = bm + ty*8 + i;
        if (row >= M) continue;
        size_t base = (size_t)row*Nn + bn + tx*8;
        #pragma unroll
        for (int h = 0; h < 2; h++){
            float4 r;
            unpack2(acc[i][h*2+0], r.x, r.y);
            unpack2(acc[i][h*2+1], r.z, r.w);
            r.x += bv[h*4+0]; r.y += bv[h*4+1];
            r.z += bv[h*4+2]; r.w += bv[h*4+3];
            if (MODE == 0){
                s1 += r.x + r.y + r.z + r.w;
                s2 += r.x*r.x + r.y*r.y + r.z*r.z + r.w*r.w;
            } else {
                float4 old = *(float4*)&Cout[base + h*4];
                r.x += old.x; r.y += old.y; r.z += old.z; r.w += old.w;
            }
            *(float4*)&Cout[base + h*4] = r;
        }
    }
    if (MODE == 0){
        #pragma unroll
        for (int o = 16; o > 0; o >>= 1){
            s1 += __shfl_xor_sync(0xFFFFFFFFu, s1, o);
            s2 += __shfl_xor_sync(0xFFFFFFFFu, s2, o);
        }
        if ((tid & 31) == 0){
            atomicAdd(&g_lnstat[0], (double)s1);
            atomicAdd(&g_lnstat[1], (double)s2);
        }
    }
}

__global__ void __launch_bounds__(256) k_gemm1(const float* __restrict__ B, const float* __restrict__ bias, int M){
    gemm128<0>(g_obuf, B, bias, g_h1, M, HH, CC, nullptr, nullptr);
}
__global__ void __launch_bounds__(256) k_gemm2(const float* __restrict__ B, const float* __restrict__ bias,
                                               const float* __restrict__ lnw, const float* __restrict__ lnb, int M){
    gemm128<1>(g_h1, B, bias, g_xbuf, M, CC, HH, lnw, lnb);
}

// out[n] = x[n,:] . lin_w + lin_b  (warp per node)
__global__ void k_final(const float* __restrict__ lw, const float* __restrict__ lb,
                        float* __restrict__ out, int N){
    int r = blockIdx.x*8 + (threadIdx.x >> 5);
    if (r >= N) return;
    int lane = threadIdx.x & 31;
    float4 v = ((const float4*)&g_xbuf[(size_t)r*CC])[lane];
    float4 w = ((const float4*)lw)[lane];
    float s = v.x*w.x + v.y*w.y + v.z*w.z + v.w*w.w;
    #pragma unroll
    for (int o = 16; o > 0; o >>= 1) s += __shfl_xor_sync(0xFFFFFFFFu, s, o);
    if (lane == 0) out[r] = s + lb[0];
}

extern "C" void kernel_launch(void* const* d_in, const int* in_sizes, int n_in,
                              void* d_out, int out_size){
    const float* x    = (const float*)d_in[0];
    const int*   src  = (const int*)  d_in[1];
    const int*   dst  = (const int*)  d_in[2];
    const float* W1   = (const float*)d_in[3];
    const float* b1   = (const float*)d_in[4];
    const float* lnw  = (const float*)d_in[5];
    const float* lnb  = (const float*)d_in[6];
    const float* W2   = (const float*)d_in[7];
    const float* b2   = (const float*)d_in[8];
    const float* t    = (const float*)d_in[9];
    const float* gnw  = (const float*)d_in[10];
    const float* gnb  = (const float*)d_in[11];
    const float* gna  = (const float*)d_in[12];
    const float* linw = (const float*)d_in[13];
    const float* linb = (const float*)d_in[14];
    float* out = (float*)d_out;

    int N = in_sizes[0]/CC;
    int E = in_sizes[1];
    int totalNC = N*CC;
    int nc_blocks = (totalNC + 255)/256;
    int e_blocks  = (E + 255)/256;

    // CSR build (per launch; deterministic; scan resets cursors)
    k_zero_deg<<<(N+255)/256, 256>>>(N);
    k_hist<<<e_blocks, 256>>>(dst, E);
    k_scan<<<1, 1024>>>(N);
    k_scatter<<<e_blocks, 256>>>(src, dst, E);

    k_copy<<<nc_blocks, 256>>>(x, totalNC);

    for (int l = 0; l < 4; l++){
        k_zero_stats<<<1, 256>>>();
        k_gn_stats<<<512, CC>>>(N);
        // k_agg: GN+ReLU fused into the gather (gn_apply eliminated)
        k_agg<<<(N+7)/8, 256>>>(t, gnw, gnb, gna, l, N);
        k_gemm1<<<dim3(HH/128, (N+127)/128), 256>>>(W1 + (size_t)l*CC*HH, b1 + (size_t)l*HH, N);
        k_gemm2<<<dim3(CC/128, (N+127)/128), 256>>>(W2 + (size_t)l*HH*CC, b2 + (size_t)l*CC,
                                                    lnw + (size_t)l*HH, lnb + (size_t)l*HH, N);
    }
    k_final<<<(N+7)/8, 256>>>(linw, linb, out, N);
}